// round 16
// baseline (speedup 1.0000x reference)
#include <cuda_runtime.h>
#include <cuda_fp16.h>

#define NB 256
#define NT 1024
#define NV 5000
#define ND 100
#define NH 64
#define NC 2

// Scratch: EW = E @ W + b, [V, H], FP16. 640 KB -> fully L2-resident.
__device__ __half g_EWh[NV * NH];

// ---------------------------------------------------------------------------
// Kernel A: EWh[v][j] = (half)(sum_d E[v][d] * W[d][j] + b[j])
// ---------------------------------------------------------------------------
__global__ void ew_kernel(const float* __restrict__ E,
                          const float* __restrict__ W,
                          const float* __restrict__ bias) {
    int v = blockIdx.x * 4 + (threadIdx.x >> 6);
    int j = threadIdx.x & 63;
    if (v >= NV) return;
    float acc = bias[j];
    const float* e = E + v * ND;
    #pragma unroll 4
    for (int d = 0; d < ND; d++)
        acc = fmaf(e[d], W[d * NH + j], acc);
    g_EWh[v * NH + j] = __float2half(acc);
}

// Packed HW tanh on both halves (MUFU.TANH f16x2): one instruction.
__device__ __forceinline__ __half2 tanh2_fast(__half2 x) {
    unsigned int yo;
    asm("tanh.approx.f16x2 %0, %1;"
        : "=r"(yo) : "r"(*reinterpret_cast<const unsigned int*>(&x)));
    return *reinterpret_cast<__half2*>(&yo);
}
__device__ __forceinline__ __half2 u2h2(unsigned int u) {
    return *reinterpret_cast<__half2*>(&u);
}

// ---------------------------------------------------------------------------
// Kernel B: masked tanh RNN, T=1024 steps + mean-pool + dense + sigmoid.
// ONE WARP PER BATCH ROW — no cross-warp exchange at all. Lane l owns the
// output pair (2l, 2l+1); U columns for both outputs live in 64 half2
// registers. h is a 128-byte warp-local smem buffer (ping-pong), accessed
// with broadcast LDS.128 and a single half2 STS per lane, ordered by
// __syncwarp ONLY (~23 cyc; no __syncthreads, no named barriers, no shfl
// merge). Per step per lane: 8 LDS.128 + 64 k-packed HFMA2 (8 accs) +
// hadd2 trees + one packed tanh.approx.f16x2 + select + STS.
// This is ISSUE-bound (~145 fma-pipe cyc/step) rather than latency-bound:
// 1 warp/SMSP suffices, so grid = 64 blocks x 128 thr (4 warps = 4
// independent rows, deterministic 1 warp/SMSP placement on 64 SMs).
// ---------------------------------------------------------------------------
__global__ void __launch_bounds__(128) rnn_kernel(
    const int* __restrict__ tokens,
    const float* __restrict__ U,
    const float* __restrict__ Wd,
    const float* __restrict__ bd,
    float* __restrict__ out)
{
    __shared__ __align__(16) __half hbuf[4][2][NH];   // per-warp ping-pong
    const int wid = threadIdx.x >> 5;
    const int l   = threadIdx.x & 31;
    const int j0  = 2 * l;                 // owned output pair (j0, j0+1)
    const int b   = blockIdx.x * 4 + wid;  // this warp's batch row

    // U columns, k-packed per output: U0[m] = (U[2m][j0], U[2m+1][j0]).
    __half2 U0[32], U1[32];
    #pragma unroll
    for (int m = 0; m < 32; m++) {
        U0[m] = __floats2half2_rn(U[(2 * m) * NH + j0],
                                  U[(2 * m + 1) * NH + j0]);
        U1[m] = __floats2half2_rn(U[(2 * m) * NH + j0 + 1],
                                  U[(2 * m + 1) * NH + j0 + 1]);
    }

    // h = 0 in buffer 0.
    *reinterpret_cast<__half2*>(&hbuf[wid][0][j0]) = __float2half2_rn(0.f);
    __syncwarp();

    const int* trow = tokens + b * NT;
    __half2 h2 = __float2half2_rn(0.f);
    float s0 = 0.f, s1 = 0.f;

    // Pipeline: tokens 3 ahead, EW pairs 2 ahead (2 steps >= L2 ~234cyc).
    int tok0 = trow[0];
    int tok1 = trow[1];
    int tok2 = trow[2];
    __half2 ew0 = *reinterpret_cast<const __half2*>(g_EWh + tok0 * NH + j0);
    __half2 ew1 = *reinterpret_cast<const __half2*>(g_EWh + tok1 * NH + j0);

    #pragma unroll 2
    for (int t = 0; t < NT; t++) {
        int t3 = (t + 3 < NT) ? (t + 3) : (NT - 1);
        int tok3 = trow[t3];
        __half2 ew2 = *reinterpret_cast<const __half2*>(g_EWh + tok2 * NH + j0);

        // Load all 64 h halves: 8 broadcast LDS.128 (conflict-free).
        const uint4* hp = reinterpret_cast<const uint4*>(hbuf[wid][t & 1]);
        uint4 w0 = hp[0], w1 = hp[1], w2 = hp[2], w3 = hp[3];
        uint4 w4 = hp[4], w5 = hp[5], w6 = hp[6], w7 = hp[7];

        __half2 z = __float2half2_rn(0.f);
        __half2 A0 = z, A1 = z, A2 = z, A3 = z;   // output j0, k-packed
        __half2 B0 = z, B1 = z, B2 = z, B3 = z;   // output j0+1, k-packed
        #define KQ(W, m0)                                                     \
            A0 = __hfma2(u2h2((W).x), U0[(m0) + 0], A0);                      \
            B0 = __hfma2(u2h2((W).x), U1[(m0) + 0], B0);                      \
            A1 = __hfma2(u2h2((W).y), U0[(m0) + 1], A1);                      \
            B1 = __hfma2(u2h2((W).y), U1[(m0) + 1], B1);                      \
            A2 = __hfma2(u2h2((W).z), U0[(m0) + 2], A2);                      \
            B2 = __hfma2(u2h2((W).z), U1[(m0) + 2], B2);                      \
            A3 = __hfma2(u2h2((W).w), U0[(m0) + 3], A3);                      \
            B3 = __hfma2(u2h2((W).w), U1[(m0) + 3], B3);
        KQ(w0, 0)  KQ(w1, 4)  KQ(w2, 8)  KQ(w3, 12)
        KQ(w4, 16) KQ(w5, 20) KQ(w6, 24) KQ(w7, 28)
        #undef KQ

        __half2 DA = __hadd2(__hadd2(A0, A1), __hadd2(A2, A3));
        __half2 DB = __hadd2(__hadd2(B0, B1), __hadd2(B2, B3));
        // Fold (even-k, odd-k) of each output, pack into one half2, add ew.
        __half2 a2 = __halves2half2(__hadd(__low2half(DA), __high2half(DA)),
                                    __hadd(__low2half(DB), __high2half(DB)));
        a2 = __hadd2(a2, ew0);
        __half2 hn2 = tanh2_fast(a2);

        // Masked recurrence: token 0 carries previous state (warp-uniform).
        if (tok0 != 0) h2 = hn2;
        float2 hf = __half22float2(h2);        // off the recurrence path
        s0 += hf.x;
        s1 += hf.y;

        // Publish into the other buffer; warp-local ordering only.
        *reinterpret_cast<__half2*>(&hbuf[wid][(t & 1) ^ 1][j0]) = h2;
        __syncwarp();

        tok0 = tok1; tok1 = tok2; tok2 = tok3;
        ew0 = ew1;  ew1 = ew2;
    }

    // Epilogue: mean pool -> dense (64 -> 2) -> sigmoid, warp-local.
    float p0 = s0 * (1.0f / NT);
    float p1 = s1 * (1.0f / NT);
    float c0 = p0 * Wd[j0 * NC + 0] + p1 * Wd[(j0 + 1) * NC + 0];
    float c1 = p0 * Wd[j0 * NC + 1] + p1 * Wd[(j0 + 1) * NC + 1];
    #pragma unroll
    for (int off = 16; off; off >>= 1) {
        c0 += __shfl_xor_sync(0xffffffffu, c0, off);
        c1 += __shfl_xor_sync(0xffffffffu, c1, off);
    }
    if (l == 0) {
        out[b * NC + 0] = 1.0f / (1.0f + expf(-(c0 + bd[0])));
        out[b * NC + 1] = 1.0f / (1.0f + expf(-(c1 + bd[1])));
    }
}

// ---------------------------------------------------------------------------
extern "C" void kernel_launch(void* const* d_in, const int* in_sizes, int n_in,
                              void* d_out, int out_size) {
    const int*   tokens = (const int*)  d_in[0];
    const float* E      = (const float*)d_in[1];
    const float* W      = (const float*)d_in[2];
    const float* U      = (const float*)d_in[3];
    const float* bias   = (const float*)d_in[4];
    const float* Wd     = (const float*)d_in[5];
    const float* bd     = (const float*)d_in[6];
    float* out = (float*)d_out;

    ew_kernel<<<(NV + 3) / 4, 256>>>(E, W, bias);
    rnn_kernel<<<NB / 4, 128>>>(tokens, U, Wd, bd, out);
}

// round 17
// speedup vs baseline: 1.3924x; 1.3924x over previous
#include <cuda_runtime.h>
#include <cuda_fp16.h>

#define NB 256
#define NT 1024
#define NV 5000
#define ND 100
#define NH 64
#define NC 2

// Scratch: EW = E @ W + b, [V, H], FP16. 640 KB -> fully L2-resident.
__device__ __half g_EWh[NV * NH];

// ---------------------------------------------------------------------------
// Kernel A: EWh[v][j] = (half)(sum_d E[v][d] * W[d][j] + b[j])
// ---------------------------------------------------------------------------
__global__ void ew_kernel(const float* __restrict__ E,
                          const float* __restrict__ W,
                          const float* __restrict__ bias) {
    int v = blockIdx.x * 4 + (threadIdx.x >> 6);
    int j = threadIdx.x & 63;
    if (v >= NV) return;
    float acc = bias[j];
    const float* e = E + v * ND;
    #pragma unroll 4
    for (int d = 0; d < ND; d++)
        acc = fmaf(e[d], W[d * NH + j], acc);
    g_EWh[v * NH + j] = __float2half(acc);
}

// HW tanh on fp16 (MUFU.TANH): lat 16, single instruction.
__device__ __forceinline__ __half tanh_fast_h(__half x) {
    __half y;
    asm("tanh.approx.f16 %0, %1;"
        : "=h"(*reinterpret_cast<unsigned short*>(&y))
        : "h"(*reinterpret_cast<const unsigned short*>(&x)));
    return y;
}
__device__ __forceinline__ __half2 u2h2(unsigned int u) {
    return *reinterpret_cast<__half2*>(&u);
}

// ---------------------------------------------------------------------------
// Kernel B: masked tanh RNN, T=1024 steps + mean-pool + dense + sigmoid.
// TWO WARPS PER ROW, LANE OWNS ONE OUTPUT WITH FULL K — the cross-lane
// merge (shfl 26cyc + 2 F2F cvts + adds) is GONE from the per-step chain;
// the price is 32 HFMA2 issue (64 cyc) per lane, which sits earlier in the
// chain where it overlaps the LDS drain. Per lane/step: 8 broadcast
// LDS.128 (full 128B h buffer) + 32 k-packed HFMA2 (8 half2 accs) +
// hadd2 tree + fold + ew hadd + tanh.approx.f16 + STS.16 (64 lanes of the
// row's warp pair write 64 distinct outputs — no predication).
// Block = 128 thr = 4 warps = 2 rows (row = wid>>1), grid = 128 <= 148
// SMs -> 1 block/SM, 1 warp/SMSP, all 256 rows resident, one cheap
// __syncthreads per step serving both rows. Skeleton (fp16 EW table,
// unroll-2 t&1 ping-pong, tokens 3 ahead / ew 2 ahead) kept verbatim.
// ---------------------------------------------------------------------------
__global__ void __launch_bounds__(128) rnn_kernel(
    const int* __restrict__ tokens,
    const float* __restrict__ U,
    const float* __restrict__ Wd,
    const float* __restrict__ bd,
    float* __restrict__ out)
{
    __shared__ __align__(16) __half hbuf[2][2][NH];   // [row][pingpong][j]
    __shared__ float red[2][2][2];                     // [row][warpinrow][c]
    const int wid = threadIdx.x >> 5;
    const int l   = threadIdx.x & 31;
    const int row = wid >> 1;              // row group 0..1
    const int wir = wid & 1;               // warp within row
    const int j   = wir * 32 + l;          // owned output (unique per lane)
    const int b   = blockIdx.x * 2 + row;  // this row's batch index

    // U column j, k-packed: Upk[m] = (U[2m][j], U[2m+1][j]). 32 regs.
    __half2 Upk[32];
    #pragma unroll
    for (int m = 0; m < 32; m++)
        Upk[m] = __floats2half2_rn(U[(2 * m) * NH + j],
                                   U[(2 * m + 1) * NH + j]);

    hbuf[row][0][j] = __float2half(0.f);
    __syncthreads();

    const int* trow = tokens + b * NT;
    __half h = __float2half(0.f);
    float s = 0.f;

    // Pipeline: tokens 3 ahead, EW rows 2 ahead (2 steps >= L2 ~234cyc).
    int tok0 = trow[0];
    int tok1 = trow[1];
    int tok2 = trow[2];
    __half ew0 = g_EWh[tok0 * NH + j];
    __half ew1 = g_EWh[tok1 * NH + j];

    #pragma unroll 2
    for (int t = 0; t < NT; t++) {
        int t3 = (t + 3 < NT) ? (t + 3) : (NT - 1);
        int tok3 = trow[t3];
        __half ew2 = g_EWh[tok2 * NH + j];

        // Full-K dot for output j: 8 broadcast LDS.128 over the 128B buffer.
        const uint4* hp = reinterpret_cast<const uint4*>(hbuf[row][t & 1]);
        uint4 w0 = hp[0], w1 = hp[1], w2 = hp[2], w3 = hp[3];
        uint4 w4 = hp[4], w5 = hp[5], w6 = hp[6], w7 = hp[7];

        __half2 z = __float2half2_rn(0.f);
        __half2 A0 = z, A1 = z, A2 = z, A3 = z;
        __half2 A4 = z, A5 = z, A6 = z, A7 = z;
        #define KQ(W, m0)                                                     \
            A0 = __hfma2(u2h2((W).x), Upk[(m0) + 0], A0);                     \
            A1 = __hfma2(u2h2((W).y), Upk[(m0) + 1], A1);                     \
            A2 = __hfma2(u2h2((W).z), Upk[(m0) + 2], A2);                     \
            A3 = __hfma2(u2h2((W).w), Upk[(m0) + 3], A3);
        #define KQ2(W, m0)                                                    \
            A4 = __hfma2(u2h2((W).x), Upk[(m0) + 0], A4);                     \
            A5 = __hfma2(u2h2((W).y), Upk[(m0) + 1], A5);                     \
            A6 = __hfma2(u2h2((W).z), Upk[(m0) + 2], A6);                     \
            A7 = __hfma2(u2h2((W).w), Upk[(m0) + 3], A7);
        KQ(w0, 0)   KQ2(w1, 4)  KQ(w2, 8)   KQ2(w3, 12)
        KQ(w4, 16)  KQ2(w5, 20) KQ(w6, 24)  KQ2(w7, 28)
        #undef KQ
        #undef KQ2

        __half2 B0 = __hadd2(A0, A1), B1 = __hadd2(A2, A3);
        __half2 B2 = __hadd2(A4, A5), B3 = __hadd2(A6, A7);
        __half2 C0 = __hadd2(B0, B1), C1 = __hadd2(B2, B3);
        __half2 D  = __hadd2(C0, C1);          // (even-k sum, odd-k sum)
        __half a_h = __hadd(__hadd(__low2half(D), __high2half(D)), ew0);
        __half hn  = tanh_fast_h(a_h);

        // Masked recurrence: token 0 carries previous state (row-uniform).
        if (tok0 != 0) h = hn;
        s += __half2float(h);                  // off the recurrence path

        // Publish: every lane writes its own output. One barrier, both rows.
        hbuf[row][(t & 1) ^ 1][j] = h;
        __syncthreads();

        tok0 = tok1; tok1 = tok2; tok2 = tok3;
        ew0 = ew1;  ew1 = ew2;
    }

    // Epilogue: mean pool -> dense (64 -> 2) -> sigmoid, per row.
    float p  = s * (1.0f / NT);
    float c0 = p * Wd[j * NC + 0];
    float c1 = p * Wd[j * NC + 1];
    #pragma unroll
    for (int off = 16; off; off >>= 1) {
        c0 += __shfl_xor_sync(0xffffffffu, c0, off);
        c1 += __shfl_xor_sync(0xffffffffu, c1, off);
    }
    if (l == 0) { red[row][wir][0] = c0; red[row][wir][1] = c1; }
    __syncthreads();
    if (l == 0 && wir == 0) {
        float C0 = red[row][0][0] + red[row][1][0] + bd[0];
        float C1 = red[row][0][1] + red[row][1][1] + bd[1];
        out[b * NC + 0] = 1.0f / (1.0f + expf(-C0));
        out[b * NC + 1] = 1.0f / (1.0f + expf(-C1));
    }
}

// ---------------------------------------------------------------------------
extern "C" void kernel_launch(void* const* d_in, const int* in_sizes, int n_in,
                              void* d_out, int out_size) {
    const int*   tokens = (const int*)  d_in[0];
    const float* E      = (const float*)d_in[1];
    const float* W      = (const float*)d_in[2];
    const float* U      = (const float*)d_in[3];
    const float* bias   = (const float*)d_in[4];
    const float* Wd     = (const float*)d_in[5];
    const float* bd     = (const float*)d_in[6];
    float* out = (float*)d_out;

    ew_kernel<<<(NV + 3) / 4, 256>>>(E, W, bias);
    rnn_kernel<<<NB / 2, 128>>>(tokens, U, Wd, bd, out);
}